// round 15
// baseline (speedup 1.0000x reference)
#include <cuda_runtime.h>
#include <cuda_fp16.h>

#define N_USERS 200000
#define N_SPOTS 50000
#define N_NODES (N_USERS + N_SPOTS)
#define N_EDGES 3200000
#define D 64
#define D4 (D / 4)

// Fixed-stride adjacency. Degrees ~ Poisson(16)/Poisson(64); caps 96/192 have
// ~e^-50 overflow probability; writes are bounds-guarded (clamped, never OOB).
// Caps are multiples of 8 (chunk size).
#define CAP_U 96
#define CAP_S 192

#define UG_BLOCKS 6250   // 8 warps * 4 users/warp = 32 users per block
#define SG_BLOCKS 1563   // 8 warps * 4 spots/warp = 32 spots per block (last partial)

// Scratch (__device__ globals; allocations forbidden).
__device__ int    g_cnt[N_NODES];            // [users | spots]
__device__ float  g_isq[N_NODES];
__device__ int    g_adj_u[N_USERS * CAP_U];  // user -> spot partners
__device__ int    g_adj_s[N_SPOTS * CAP_S];  // spot -> user partners
__device__ __half g_ux[(N_USERS + 1) * D];   // pre-scaled user rows + zero dummy row
__device__ __half g_sx[(N_SPOTS + 1) * D];   // pre-scaled spot rows + zero dummy row

// Zero counters and the two dummy rows (defensive; they are never overwritten).
__global__ void __launch_bounds__(256) zero_kernel() {
    int i = blockIdx.x * blockDim.x + threadIdx.x;
    if (i < N_NODES) g_cnt[i] = 0;
    else if (i < N_NODES + D) g_sx[N_SPOTS * D + (i - N_NODES)] = __float2half(0.f);
    else if (i < N_NODES + 2 * D) g_ux[N_USERS * D + (i - N_NODES - D)] = __float2half(0.f);
}

// Fused degree+fill: one atomic produces slot AND final degree. 4 edges per
// thread via int4 loads; 8 independent atomics then 8 guarded stores.
__global__ void __launch_bounds__(256) fill_kernel(const int4* __restrict__ user_idx4,
                                                   const int4* __restrict__ spot_idx4) {
    int t = blockIdx.x * blockDim.x + threadIdx.x;
    if (t >= N_EDGES / 4) return;
    int4 u = __ldg(&user_idx4[t]);
    int4 s = __ldg(&spot_idx4[t]);

    int au0 = atomicAdd(&g_cnt[u.x], 1);
    int au1 = atomicAdd(&g_cnt[u.y], 1);
    int au2 = atomicAdd(&g_cnt[u.z], 1);
    int au3 = atomicAdd(&g_cnt[u.w], 1);
    int as0 = atomicAdd(&g_cnt[N_USERS + s.x], 1);
    int as1 = atomicAdd(&g_cnt[N_USERS + s.y], 1);
    int as2 = atomicAdd(&g_cnt[N_USERS + s.z], 1);
    int as3 = atomicAdd(&g_cnt[N_USERS + s.w], 1);

    if (au0 < CAP_U) g_adj_u[u.x * CAP_U + au0] = s.x;
    if (au1 < CAP_U) g_adj_u[u.y * CAP_U + au1] = s.y;
    if (au2 < CAP_U) g_adj_u[u.z * CAP_U + au2] = s.z;
    if (au3 < CAP_U) g_adj_u[u.w * CAP_U + au3] = s.w;
    if (as0 < CAP_S) g_adj_s[s.x * CAP_S + as0] = u.x;
    if (as1 < CAP_S) g_adj_s[s.y * CAP_S + as1] = u.y;
    if (as2 < CAP_S) g_adj_s[s.z * CAP_S + as2] = u.z;
    if (as3 < CAP_S) g_adj_s[s.w * CAP_S + as3] = u.w;
}

// Fused prescale + pad. One thread per quarter-row (node = i>>4):
//  - converts its 4 floats to fp16, scaled by rsqrt(degree)
//  - thread (i&15)==0 writes g_isq
//  - threads (i&15)<8 pad the node's adjacency tail to a multiple of 8 with
//    the dummy partner (whose fp16 row is all zeros).
__global__ void __launch_bounds__(256) prescale_pad_kernel(const float* __restrict__ user_x,
                                                           const float* __restrict__ spot_x) {
    int i = blockIdx.x * blockDim.x + threadIdx.x;
    if (i >= N_NODES * D4) return;
    int node = i >> 4;
    int sub = i & 15;
    int dg = g_cnt[node];
    float q = rsqrtf(dg == 0 ? 1e-6f : (float)dg);
    if (sub == 0) g_isq[node] = q;

    if (sub < 8) {
        if (node < N_USERS) {
            int e = min(dg, CAP_U);
            if (e & 7) {
                int pos = (e & ~7) + sub;
                if (pos >= e) g_adj_u[node * CAP_U + pos] = N_SPOTS;   // dummy spot
            }
        } else {
            int m = node - N_USERS;
            int e = min(dg, CAP_S);
            if (e & 7) {
                int pos = (e & ~7) + sub;
                if (pos >= e) g_adj_s[m * CAP_S + pos] = N_USERS;      // dummy user
            }
        }
    }

    float4 v;
    __half2* dst;
    if (node < N_USERS) {
        v = __ldg(&((const float4*)user_x)[i]);
        dst = (__half2*)g_ux + i * 2;
    } else {
        int j = i - N_USERS * D4;
        v = __ldg(&((const float4*)spot_x)[j]);
        dst = (__half2*)g_sx + j * 2;
    }
    dst[0] = __floats2half2_rn(v.x * q, v.y * q);
    dst[1] = __floats2half2_rn(v.z * q, v.w * q);
}

// Per-group gather core: 8 lanes per node, uint4 (8 halves) per lane.
// fp16 accumulation across up to TWO 8-edge chunks (16 edges) before flushing
// to fp32. Lists are 8-padded so chunks are unpredicated.
struct Acc8 {
    float a[8];
    __device__ __forceinline__ void init() {
        #pragma unroll
        for (int j = 0; j < 8; ++j) a[j] = 0.f;
    }
};

__device__ __forceinline__ void gather_node(const int* __restrict__ adj, int chunks,
                                            const uint4* __restrict__ px,
                                            unsigned gmask, int gbase, int col,
                                            Acc8& acc) {
    __half2 h0 = __float2half2_rn(0.f), h1 = h0, h2 = h0, h3 = h0;
    for (int c = 0; c < chunks; ++c) {
        int p = __ldg(&adj[c * 8 + col]);
        #pragma unroll
        for (int k = 0; k < 8; ++k) {
            int pk = __shfl_sync(gmask, p, gbase + k);
            uint4 v = __ldg(&px[pk * 8 + col]);
            h0 = __hadd2(h0, *reinterpret_cast<__half2*>(&v.x));
            h1 = __hadd2(h1, *reinterpret_cast<__half2*>(&v.y));
            h2 = __hadd2(h2, *reinterpret_cast<__half2*>(&v.z));
            h3 = __hadd2(h3, *reinterpret_cast<__half2*>(&v.w));
        }
        if ((c & 1) || (c + 1 == chunks)) {   // flush every 2 chunks (<=16 fp16 adds)
            float2 f;
            f = __half22float2(h0); acc.a[0] += f.x; acc.a[1] += f.y;
            f = __half22float2(h1); acc.a[2] += f.x; acc.a[3] += f.y;
            f = __half22float2(h2); acc.a[4] += f.x; acc.a[5] += f.y;
            f = __half22float2(h3); acc.a[6] += f.x; acc.a[7] += f.y;
            h0 = h1 = h2 = h3 = __float2half2_rn(0.f);
        }
    }
}

// Blocks [0, UG_BLOCKS): 4 users per warp (8 lanes each).
// Blocks [UG_BLOCKS, ...): 4 spots per warp. 8 blocks/SM => 100% occupancy.
__global__ void __launch_bounds__(256, 8) gather_kernel(float* __restrict__ out) {
    int wib = threadIdx.x >> 5;
    int lane = threadIdx.x & 31;
    int group = lane >> 3;       // 0..3
    int col = lane & 7;          // uint4 chunk within row
    int gbase = group << 3;
    unsigned gmask = 0xFFu << gbase;

    Acc8 acc;
    acc.init();
    float sc;
    int n_out;

    if (blockIdx.x < UG_BLOCKS) {
        int n = (blockIdx.x * 8 + wib) * 4 + group;     // < N_USERS exactly
        int end = min(g_cnt[n], CAP_U);
        int chunks = (end + 7) >> 3;                    // padded region is valid
        gather_node(g_adj_u + n * CAP_U, chunks, (const uint4*)g_sx,
                    gmask, gbase, col, acc);
        sc = g_isq[n];
        n_out = n;
    } else {
        int m = ((blockIdx.x - UG_BLOCKS) * 8 + wib) * 4 + group;
        if (m >= N_SPOTS) return;                        // whole group exits
        int end = min(g_cnt[N_USERS + m], CAP_S);
        int chunks = (end + 7) >> 3;
        gather_node(g_adj_s + m * CAP_S, chunks, (const uint4*)g_ux,
                    gmask, gbase, col, acc);
        sc = g_isq[N_USERS + m];
        n_out = N_USERS + m;
    }

    float4* o = (float4*)out + n_out * 16 + col * 2;
    o[0] = make_float4(acc.a[0] * sc, acc.a[1] * sc, acc.a[2] * sc, acc.a[3] * sc);
    o[1] = make_float4(acc.a[4] * sc, acc.a[5] * sc, acc.a[6] * sc, acc.a[7] * sc);
}

extern "C" void kernel_launch(void* const* d_in, const int* in_sizes, int n_in,
                              void* d_out, int out_size) {
    const float* user_x   = (const float*)d_in[0];
    const float* spot_x   = (const float*)d_in[1];
    const int*   user_idx = (const int*)d_in[2];
    const int*   spot_idx = (const int*)d_in[3];
    float* out = (float*)d_out;

    zero_kernel<<<(N_NODES + 2 * D + 255) / 256, 256>>>();

    int e4 = N_EDGES / 4;  // 800000
    fill_kernel<<<(e4 + 255) / 256, 256>>>((const int4*)user_idx, (const int4*)spot_idx);

    int ps_threads = N_NODES * D4;
    prescale_pad_kernel<<<(ps_threads + 255) / 256, 256>>>(user_x, spot_x);

    gather_kernel<<<UG_BLOCKS + SG_BLOCKS, 256>>>(out);
}

// round 16
// speedup vs baseline: 1.2274x; 1.2274x over previous
#include <cuda_runtime.h>
#include <cuda_fp16.h>

#define N_USERS 200000
#define N_SPOTS 50000
#define N_NODES (N_USERS + N_SPOTS)
#define N_EDGES 3200000
#define D 64
#define D4 (D / 4)

// Fixed-stride adjacency. Degrees ~ Poisson(16)/Poisson(64); caps 96/192 have
// ~e^-50 overflow probability; writes are bounds-guarded (clamped, never OOB).
// Caps are multiples of 8 (chunk size).
#define CAP_U 96
#define CAP_S 192

#define UG_BLOCKS 6250   // 8 warps * 4 users/warp = 32 users per block
#define SG_BLOCKS 1563   // 8 warps * 4 spots/warp = 32 spots per block (last partial)

// Scratch (__device__ globals; allocations forbidden).
__device__ int    g_cnt[N_NODES];            // [users | spots]
__device__ float  g_isq[N_NODES];
__device__ int    g_adj_u[N_USERS * CAP_U];  // user -> spot partners
__device__ int    g_adj_s[N_SPOTS * CAP_S];  // spot -> user partners
__device__ __half g_ux[(N_USERS + 1) * D];   // pre-scaled user rows + zero dummy row
__device__ __half g_sx[(N_SPOTS + 1) * D];   // pre-scaled spot rows + zero dummy row

// Zero counters and the two dummy rows (defensive; they are never overwritten).
__global__ void __launch_bounds__(256) zero_kernel() {
    int i = blockIdx.x * blockDim.x + threadIdx.x;
    if (i < N_NODES) g_cnt[i] = 0;
    else if (i < N_NODES + D) g_sx[N_SPOTS * D + (i - N_NODES)] = __float2half(0.f);
    else if (i < N_NODES + 2 * D) g_ux[N_USERS * D + (i - N_NODES - D)] = __float2half(0.f);
}

// Fused degree+fill: one atomic produces slot AND final degree. 4 edges per
// thread via int4 loads; 8 independent atomics then 8 guarded stores.
__global__ void __launch_bounds__(256) fill_kernel(const int4* __restrict__ user_idx4,
                                                   const int4* __restrict__ spot_idx4) {
    int t = blockIdx.x * blockDim.x + threadIdx.x;
    if (t >= N_EDGES / 4) return;
    int4 u = __ldg(&user_idx4[t]);
    int4 s = __ldg(&spot_idx4[t]);

    int au0 = atomicAdd(&g_cnt[u.x], 1);
    int au1 = atomicAdd(&g_cnt[u.y], 1);
    int au2 = atomicAdd(&g_cnt[u.z], 1);
    int au3 = atomicAdd(&g_cnt[u.w], 1);
    int as0 = atomicAdd(&g_cnt[N_USERS + s.x], 1);
    int as1 = atomicAdd(&g_cnt[N_USERS + s.y], 1);
    int as2 = atomicAdd(&g_cnt[N_USERS + s.z], 1);
    int as3 = atomicAdd(&g_cnt[N_USERS + s.w], 1);

    if (au0 < CAP_U) g_adj_u[u.x * CAP_U + au0] = s.x;
    if (au1 < CAP_U) g_adj_u[u.y * CAP_U + au1] = s.y;
    if (au2 < CAP_U) g_adj_u[u.z * CAP_U + au2] = s.z;
    if (au3 < CAP_U) g_adj_u[u.w * CAP_U + au3] = s.w;
    if (as0 < CAP_S) g_adj_s[s.x * CAP_S + as0] = u.x;
    if (as1 < CAP_S) g_adj_s[s.y * CAP_S + as1] = u.y;
    if (as2 < CAP_S) g_adj_s[s.z * CAP_S + as2] = u.z;
    if (as3 < CAP_S) g_adj_s[s.w * CAP_S + as3] = u.w;
}

// Fused prescale + pad (no prefetch anywhere). One thread per quarter-row:
//  - converts its 4 floats to fp16, scaled by rsqrt(degree)
//  - thread (i&15)==0 writes g_isq
//  - threads (i&15)<8 pad the node's adjacency tail to a multiple of 8 with
//    the dummy partner (whose fp16 row is all zeros).
__global__ void __launch_bounds__(256) prescale_pad_kernel(const float* __restrict__ user_x,
                                                           const float* __restrict__ spot_x) {
    int i = blockIdx.x * blockDim.x + threadIdx.x;
    if (i >= N_NODES * D4) return;
    int node = i >> 4;
    int sub = i & 15;
    int dg = g_cnt[node];
    float q = rsqrtf(dg == 0 ? 1e-6f : (float)dg);
    if (sub == 0) g_isq[node] = q;

    if (sub < 8) {
        if (node < N_USERS) {
            int e = min(dg, CAP_U);
            if (e & 7) {
                int pos = (e & ~7) + sub;
                if (pos >= e) g_adj_u[node * CAP_U + pos] = N_SPOTS;   // dummy spot
            }
        } else {
            int m = node - N_USERS;
            int e = min(dg, CAP_S);
            if (e & 7) {
                int pos = (e & ~7) + sub;
                if (pos >= e) g_adj_s[m * CAP_S + pos] = N_USERS;      // dummy user
            }
        }
    }

    float4 v;
    __half2* dst;
    if (node < N_USERS) {
        v = __ldg(&((const float4*)user_x)[i]);
        dst = (__half2*)g_ux + i * 2;
    } else {
        int j = i - N_USERS * D4;
        v = __ldg(&((const float4*)spot_x)[j]);
        dst = (__half2*)g_sx + j * 2;
    }
    dst[0] = __floats2half2_rn(v.x * q, v.y * q);
    dst[1] = __floats2half2_rn(v.z * q, v.w * q);
}

// Per-group gather core (R13 structure): 8 lanes per node, uint4 (8 halves)
// per lane. fp16 accumulation within each 8-edge chunk, flushed to fp32 per
// chunk (short accumulator live range => low regs). Lists are 8-padded, so
// the loop is fully unrolled and unpredicated. No prefetch.
struct Acc8 {
    float a[8];
    __device__ __forceinline__ void init() {
        #pragma unroll
        for (int j = 0; j < 8; ++j) a[j] = 0.f;
    }
};

__device__ __forceinline__ void gather_node(const int* __restrict__ adj, int chunks,
                                            const uint4* __restrict__ px,
                                            unsigned gmask, int gbase, int col,
                                            Acc8& acc) {
    for (int c = 0; c < chunks; ++c) {
        int p = __ldg(&adj[c * 8 + col]);
        __half2 h0 = __float2half2_rn(0.f), h1 = h0, h2 = h0, h3 = h0;
        #pragma unroll
        for (int k = 0; k < 8; ++k) {
            int pk = __shfl_sync(gmask, p, gbase + k);
            uint4 v = __ldg(&px[pk * 8 + col]);
            h0 = __hadd2(h0, *reinterpret_cast<__half2*>(&v.x));
            h1 = __hadd2(h1, *reinterpret_cast<__half2*>(&v.y));
            h2 = __hadd2(h2, *reinterpret_cast<__half2*>(&v.z));
            h3 = __hadd2(h3, *reinterpret_cast<__half2*>(&v.w));
        }
        float2 f;
        f = __half22float2(h0); acc.a[0] += f.x; acc.a[1] += f.y;
        f = __half22float2(h1); acc.a[2] += f.x; acc.a[3] += f.y;
        f = __half22float2(h2); acc.a[4] += f.x; acc.a[5] += f.y;
        f = __half22float2(h3); acc.a[6] += f.x; acc.a[7] += f.y;
    }
}

// Blocks [0, UG_BLOCKS): 4 users per warp (8 lanes each).
// Blocks [UG_BLOCKS, ...): 4 spots per warp. 6 blocks/SM (regs ~40, no spills).
__global__ void __launch_bounds__(256, 6) gather_kernel(float* __restrict__ out) {
    int wib = threadIdx.x >> 5;
    int lane = threadIdx.x & 31;
    int group = lane >> 3;       // 0..3
    int col = lane & 7;          // uint4 chunk within row
    int gbase = group << 3;
    unsigned gmask = 0xFFu << gbase;

    Acc8 acc;
    acc.init();
    float sc;
    int n_out;

    if (blockIdx.x < UG_BLOCKS) {
        int n = (blockIdx.x * 8 + wib) * 4 + group;     // < N_USERS exactly
        int end = min(g_cnt[n], CAP_U);
        int chunks = (end + 7) >> 3;                    // padded region is valid
        gather_node(g_adj_u + n * CAP_U, chunks, (const uint4*)g_sx,
                    gmask, gbase, col, acc);
        sc = g_isq[n];
        n_out = n;
    } else {
        int m = ((blockIdx.x - UG_BLOCKS) * 8 + wib) * 4 + group;
        if (m >= N_SPOTS) return;                        // whole group exits
        int end = min(g_cnt[N_USERS + m], CAP_S);
        int chunks = (end + 7) >> 3;
        gather_node(g_adj_s + m * CAP_S, chunks, (const uint4*)g_ux,
                    gmask, gbase, col, acc);
        sc = g_isq[N_USERS + m];
        n_out = N_USERS + m;
    }

    float4* o = (float4*)out + n_out * 16 + col * 2;
    o[0] = make_float4(acc.a[0] * sc, acc.a[1] * sc, acc.a[2] * sc, acc.a[3] * sc);
    o[1] = make_float4(acc.a[4] * sc, acc.a[5] * sc, acc.a[6] * sc, acc.a[7] * sc);
}

extern "C" void kernel_launch(void* const* d_in, const int* in_sizes, int n_in,
                              void* d_out, int out_size) {
    const float* user_x   = (const float*)d_in[0];
    const float* spot_x   = (const float*)d_in[1];
    const int*   user_idx = (const int*)d_in[2];
    const int*   spot_idx = (const int*)d_in[3];
    float* out = (float*)d_out;

    zero_kernel<<<(N_NODES + 2 * D + 255) / 256, 256>>>();

    int e4 = N_EDGES / 4;  // 800000
    fill_kernel<<<(e4 + 255) / 256, 256>>>((const int4*)user_idx, (const int4*)spot_idx);

    int ps_threads = N_NODES * D4;
    prescale_pad_kernel<<<(ps_threads + 255) / 256, 256>>>(user_x, spot_x);

    gather_kernel<<<UG_BLOCKS + SG_BLOCKS, 256>>>(out);
}